// round 5
// baseline (speedup 1.0000x reference)
#include <cuda_runtime.h>
#include <cuda.h>
#include <cstdint>

#define D_IN      1280
#define BM        128
#define BK        32
#define NSTAGE    4
#define NTHREADS  256
#define XTILE_FLOATS (BM * BK)                    // 4096 floats = 16 KB
#define WTILE_FLOATS (64 * BK)                    // 2048 floats = 8 KB
#define STAGE_FLOATS (XTILE_FLOATS + WTILE_FLOATS)// 6144 floats = 24 KB
#define STAGE_BYTES  (STAGE_FLOATS * 4)
#define HS_STRIDE 65

// ---------------- PTX helpers ----------------
__device__ __forceinline__ unsigned f2tf(float f) {
    unsigned r; asm("cvt.rna.tf32.f32 %0, %1;\n" : "=r"(r) : "f"(f)); return r;
}
__device__ __forceinline__ void mma8(float& c0, float& c1, float& c2, float& c3,
                                     unsigned a0, unsigned a1, unsigned a2, unsigned a3,
                                     unsigned b0, unsigned b1) {
    asm volatile("mma.sync.aligned.m16n8k8.row.col.f32.tf32.tf32.f32 "
                 "{%0,%1,%2,%3}, {%4,%5,%6,%7}, {%8,%9}, {%0,%1,%2,%3};\n"
                 : "+f"(c0), "+f"(c1), "+f"(c2), "+f"(c3)
                 : "r"(a0), "r"(a1), "r"(a2), "r"(a3), "r"(b0), "r"(b1));
}
__device__ __forceinline__ void mbar_wait(unsigned addr, unsigned parity) {
    asm volatile(
        "{\n\t.reg .pred P1;\n\t"
        "WAIT_%=:\n\t"
        "mbarrier.try_wait.parity.acquire.cta.shared::cta.b64 P1, [%0], %1, 0x989680;\n\t"
        "@P1 bra.uni DONE_%=;\n\t"
        "bra.uni WAIT_%=;\n\t"
        "DONE_%=:\n\t}"
        :: "r"(addr), "r"(parity) : "memory");
}
__device__ __forceinline__ void tma2d(unsigned saddr, const CUtensorMap* tm,
                                      int cx, int cy, unsigned mbar) {
    asm volatile("cp.async.bulk.tensor.2d.shared::cta.global.tile.mbarrier::complete_tx::bytes "
                 "[%0], [%1, {%2, %3}], [%4];"
                 :: "r"(saddr), "l"(tm), "r"(cx), "r"(cy), "r"(mbar) : "memory");
}

// ---------------- fused kernel ----------------
// h = relu(x@W1^T+b1); h = h*scale+shift (BN eval); xq = tanh(h@W2^T+b2);
// 4-qubit sim with angles pi*tanh(xq); out = z@W3^T+b3.
__global__ __launch_bounds__(NTHREADS, 2)
void qh_fused_kernel(const __grid_constant__ CUtensorMap tmx,
                     const __grid_constant__ CUtensorMap tmw,
                     const float* __restrict__ b1,  const float* __restrict__ bn_g,
                     const float* __restrict__ bn_b,const float* __restrict__ bn_m,
                     const float* __restrict__ bn_v,const float* __restrict__ W2,
                     const float* __restrict__ b2,  const float* __restrict__ qw,
                     const float* __restrict__ W3,  const float* __restrict__ b3,
                     float* __restrict__ out, int B)
{
    extern __shared__ float smem_raw[];
    float* smem = (float*)(((uintptr_t)smem_raw + 1023) & ~(uintptr_t)1023); // SW128 tile base
    __shared__ __align__(8) unsigned long long mbar[NSTAGE];
    __shared__ float bias_s[64], scale_s[64], shift_s[64];
    __shared__ float w2s[256], b2s[4], w3s[40], b3s[10];
    __shared__ float ryc[8], rys[8], rzc[8], rzs[8];

    const int tid = threadIdx.x;
    const int blockRow = blockIdx.x * BM;

    // ---- per-block parameter prep (tiny) ----
    if (tid < 64) {
        float rs = rsqrtf(bn_v[tid] + 1e-5f);
        float sc = bn_g[tid] * rs;
        scale_s[tid] = sc;
        shift_s[tid] = bn_b[tid] - bn_m[tid] * sc;
        bias_s[tid]  = b1[tid];
    }
    if (tid < 256) w2s[tid] = W2[tid];
    if (tid < 16) {
        int l = (tid >> 2) & 1, qi = tid & 3, isRz = tid >> 3;
        float half = 0.5f * qw[l * 8 + qi * 2 + isRz];
        float sv, cv; sincosf(half, &sv, &cv);
        if (isRz) { rzc[l*4+qi] = cv; rzs[l*4+qi] = sv; }
        else      { ryc[l*4+qi] = cv; rys[l*4+qi] = sv; }
    }
    if (tid < 40) w3s[tid] = W3[tid];
    if (tid < 10) b3s[tid] = b3[tid];
    if (tid < 4)  b2s[tid] = b2[tid];

    // ---- mbarrier init ----
    if (tid == 0) {
        #pragma unroll
        for (int s = 0; s < NSTAGE; s++) {
            unsigned a = (unsigned)__cvta_generic_to_shared(&mbar[s]);
            asm volatile("mbarrier.init.shared.b64 [%0], 1;" :: "r"(a) : "memory");
        }
        asm volatile("fence.proxy.async.shared::cta;" ::: "memory");
    }
    __syncthreads();

    const int KT = D_IN / BK;   // 40
    auto issue_stage = [&](int st) {
        float* xs = smem + (st & (NSTAGE - 1)) * STAGE_FLOATS;
        unsigned xaddr = (unsigned)__cvta_generic_to_shared(xs);
        unsigned waddr = xaddr + XTILE_FLOATS * 4;
        unsigned ma = (unsigned)__cvta_generic_to_shared(&mbar[st & (NSTAGE - 1)]);
        asm volatile("mbarrier.arrive.expect_tx.shared.b64 _, [%0], %1;"
                     :: "r"(ma), "r"((unsigned)STAGE_BYTES) : "memory");
        tma2d(xaddr, &tmx, st * BK, blockRow, ma);
        tma2d(waddr, &tmw, st * BK, 0, ma);
    };
    if (tid == 0) {
        #pragma unroll
        for (int s = 0; s < NSTAGE - 1; s++) issue_stage(s);
    }

    const int lane = tid & 31, warp = tid >> 5;      // 8 warps
    const int warpRow = warp >> 1;                   // 0..3 -> 32-row band
    const int warpCol = warp & 1;                    // 0..1 -> 32-col band
    const int g = lane >> 2, t = lane & 3;

    float acc[2][4][4];
    #pragma unroll
    for (int mt = 0; mt < 2; mt++)
        #pragma unroll
        for (int nt = 0; nt < 4; nt++)
            #pragma unroll
            for (int k = 0; k < 4; k++) acc[mt][nt][k] = 0.f;

    for (int kt = 0; kt < KT; kt++) {
        const int buf = kt & (NSTAGE - 1);
        const unsigned phase = (kt >> 2) & 1;
        mbar_wait((unsigned)__cvta_generic_to_shared(&mbar[buf]), phase);
        __syncthreads();                 // all warps done with buffer (kt-1)&3
        if (tid == 0 && kt + NSTAGE - 1 < KT) issue_stage(kt + NSTAGE - 1);

        // SW128-swizzled tiles: float (r, c) at r*32 + (((c>>2) ^ (r&7))<<2) + (c&3)
        const float* xs = smem + buf * STAGE_FLOATS;
        const float* ws = xs + XTILE_FLOATS;
        const float* xsb = xs + (warpRow * 32 + g) * 32 + t;   // (r&7) == g for all our rows
        const float* wsb = ws + (warpCol * 32 + g) * 32 + t;

        #pragma unroll
        for (int k8 = 0; k8 < BK / 8; k8++) {
            const int c0 = ((2 * k8)     ^ g) << 2;
            const int c1 = ((2 * k8 + 1) ^ g) << 2;
            unsigned a[2][4], b[4][2];
            #pragma unroll
            for (int mt = 0; mt < 2; mt++) {
                const float* p = xsb + mt * 16 * 32;
                a[mt][0] = f2tf(p[c0]);
                a[mt][1] = f2tf(p[8 * 32 + c0]);
                a[mt][2] = f2tf(p[c1]);
                a[mt][3] = f2tf(p[8 * 32 + c1]);
            }
            #pragma unroll
            for (int nt = 0; nt < 4; nt++) {
                const float* p = wsb + nt * 8 * 32;
                b[nt][0] = f2tf(p[c0]);
                b[nt][1] = f2tf(p[c1]);
            }
            #pragma unroll
            for (int mt = 0; mt < 2; mt++)
                #pragma unroll
                for (int nt = 0; nt < 4; nt++)
                    mma8(acc[mt][nt][0], acc[mt][nt][1], acc[mt][nt][2], acc[mt][nt][3],
                         a[mt][0], a[mt][1], a[mt][2], a[mt][3], b[nt][0], b[nt][1]);
        }
    }
    __syncthreads();   // all warps done reading stage buffers

    // ---- epilogue: bias+relu+BN, stage h-tile to smem ----
    float* hs = smem;  // overlay (33 KB << 96 KB pipeline buffers)
    #pragma unroll
    for (int mt = 0; mt < 2; mt++) {
        const int r0 = warpRow * 32 + mt * 16 + g;
        #pragma unroll
        for (int nt = 0; nt < 4; nt++) {
            const int n0 = warpCol * 32 + nt * 8 + t * 2;
            float s0 = scale_s[n0],  s1 = scale_s[n0 + 1];
            float f0 = shift_s[n0],  f1 = shift_s[n0 + 1];
            float bi0 = bias_s[n0],  bi1 = bias_s[n0 + 1];
            hs[r0 * HS_STRIDE + n0]           = fmaxf(acc[mt][nt][0] + bi0, 0.f) * s0 + f0;
            hs[r0 * HS_STRIDE + n0 + 1]       = fmaxf(acc[mt][nt][1] + bi1, 0.f) * s1 + f1;
            hs[(r0 + 8) * HS_STRIDE + n0]     = fmaxf(acc[mt][nt][2] + bi0, 0.f) * s0 + f0;
            hs[(r0 + 8) * HS_STRIDE + n0 + 1] = fmaxf(acc[mt][nt][3] + bi1, 0.f) * s1 + f1;
        }
    }
    __syncthreads();

    // ---- one thread per row: W2 proj + 4-qubit statevector sim + W3 out ----
    const int gr = blockRow + tid;
    if (tid < BM && gr < B) {
        float aq0 = b2s[0], aq1 = b2s[1], aq2 = b2s[2], aq3 = b2s[3];
        const float* hr = hs + tid * HS_STRIDE;
        #pragma unroll
        for (int j = 0; j < 64; j++) {
            float v = hr[j];
            aq0 += v * w2s[j];        aq1 += v * w2s[64 + j];
            aq2 += v * w2s[128 + j];  aq3 += v * w2s[192 + j];
        }
        float aq[4] = {aq0, aq1, aq2, aq3};
        float ci[4], si[4];
        #pragma unroll
        for (int i = 0; i < 4; i++) {
            // half-angle = (pi/2) * tanh(tanh(pre))  (double tanh is faithful to reference)
            float hl = 1.57079632679489662f * tanhf(tanhf(aq[i]));
            sincosf(hl, &si[i], &ci[i]);
        }
        // initial RY layer on |0000>: real product state. bit of wire i = (s >> (3-i)) & 1
        float re[16], im[16];
        #pragma unroll
        for (int s = 0; s < 16; s++) {
            float p = ((s >> 3) & 1 ? si[0] : ci[0]);
            p *=      ((s >> 2) & 1 ? si[1] : ci[1]);
            p *=      ((s >> 1) & 1 ? si[2] : ci[2]);
            p *=      ((s     ) & 1 ? si[3] : ci[3]);
            re[s] = p; im[s] = 0.f;
        }
        #pragma unroll
        for (int l = 0; l < 2; l++) {
            #pragma unroll
            for (int qi = 0; qi < 4; qi++) {
                const int m = 1 << (3 - qi);
                float c = ryc[l * 4 + qi], sv = rys[l * 4 + qi];
                #pragma unroll
                for (int s0 = 0; s0 < 16; s0++) {
                    if (!(s0 & m)) {
                        const int s1 = s0 | m;
                        float r0 = re[s0], r1 = re[s1], i0 = im[s0], i1 = im[s1];
                        re[s0] = c * r0 - sv * r1;  im[s0] = c * i0 - sv * i1;
                        re[s1] = sv * r0 + c * r1;  im[s1] = sv * i0 + c * i1;
                    }
                }
                float ch = rzc[l * 4 + qi], sh = rzs[l * 4 + qi];
                #pragma unroll
                for (int s0 = 0; s0 < 16; s0++) {
                    float r = re[s0], iz = im[s0];
                    if (!(s0 & m)) { re[s0] = r * ch + iz * sh; im[s0] = iz * ch - r * sh; }
                    else           { re[s0] = r * ch - iz * sh; im[s0] = iz * ch + r * sh; }
                }
            }
            #pragma unroll
            for (int qi = 0; qi < 4; qi++) {        // CNOT(qi, (qi+1)%4), in order
                const int mc = 1 << (3 - qi);
                const int mt_ = 1 << (3 - ((qi + 1) & 3));
                #pragma unroll
                for (int s0 = 0; s0 < 16; s0++) {
                    if ((s0 & mc) && !(s0 & mt_)) {
                        const int s1 = s0 | mt_;
                        float tr = re[s0]; re[s0] = re[s1]; re[s1] = tr;
                        float ti = im[s0]; im[s0] = im[s1]; im[s1] = ti;
                    }
                }
            }
        }
        float z0 = 0.f, z1 = 0.f, z2 = 0.f, z3 = 0.f;
        #pragma unroll
        for (int s = 0; s < 16; s++) {
            float p = re[s] * re[s] + im[s] * im[s];
            z0 += (s & 8) ? -p : p;
            z1 += (s & 4) ? -p : p;
            z2 += (s & 2) ? -p : p;
            z3 += (s & 1) ? -p : p;
        }
        #pragma unroll
        for (int c = 0; c < 10; c++) {
            out[(size_t)gr * 10 + c] = b3s[c] + w3s[c * 4 + 0] * z0 + w3s[c * 4 + 1] * z1
                                              + w3s[c * 4 + 2] * z2 + w3s[c * 4 + 3] * z3;
        }
    }
}

// ---------------- host: tensor maps + launch ----------------
typedef CUresult (*pfn_encode_t)(CUtensorMap*, CUtensorMapDataType, cuuint32_t, void*,
                                 const cuuint64_t*, const cuuint64_t*, const cuuint32_t*,
                                 const cuuint32_t*, CUtensorMapInterleave, CUtensorMapSwizzle,
                                 CUtensorMapL2promotion, CUtensorMapFloatOOBfill);

static pfn_encode_t get_encoder() {
    void* fn = nullptr;
    cudaDriverEntryPointQueryResult qr = cudaDriverEntryPointSymbolNotFound;
    // Preferred (CUDA >= 12.5, present in 13.x):
    if (cudaGetDriverEntryPointByVersion("cuTensorMapEncodeTiled", &fn, 12000,
                                         cudaEnableDefault, &qr) == cudaSuccess &&
        qr == cudaDriverEntryPointSuccess && fn) return (pfn_encode_t)fn;
    fn = nullptr;
    // Legacy fallback:
    if (cudaGetDriverEntryPoint("cuTensorMapEncodeTiled", &fn,
                                cudaEnableDefault, &qr) == cudaSuccess &&
        qr == cudaDriverEntryPointSuccess && fn) return (pfn_encode_t)fn;
    return nullptr;
}

static void make_map_2d(CUtensorMap* m, pfn_encode_t enc, void* ptr,
                        uint64_t d0, uint64_t d1, uint32_t b0, uint32_t b1) {
    cuuint64_t dims[2]    = {d0, d1};
    cuuint64_t strides[1] = {d0 * 4};
    cuuint32_t box[2]     = {b0, b1};
    cuuint32_t es[2]      = {1, 1};
    enc(m, CU_TENSOR_MAP_DATA_TYPE_FLOAT32, 2, ptr, dims, strides, box, es,
        CU_TENSOR_MAP_INTERLEAVE_NONE, CU_TENSOR_MAP_SWIZZLE_128B,
        CU_TENSOR_MAP_L2_PROMOTION_L2_128B, CU_TENSOR_MAP_FLOAT_OOB_FILL_NONE);
}

extern "C" void kernel_launch(void* const* d_in, const int* in_sizes, int n_in,
                              void* d_out, int out_size) {
    void* x    = d_in[0];
    void* W1   = d_in[1];
    const float* b1   = (const float*)d_in[2];
    const float* bn_g = (const float*)d_in[3];
    const float* bn_b = (const float*)d_in[4];
    const float* bn_m = (const float*)d_in[5];
    const float* bn_v = (const float*)d_in[6];
    const float* W2   = (const float*)d_in[7];
    const float* b2   = (const float*)d_in[8];
    const float* qw   = (const float*)d_in[9];
    const float* W3   = (const float*)d_in[10];
    const float* b3   = (const float*)d_in[11];
    float* out = (float*)d_out;

    const int B = in_sizes[0] / D_IN;
    const int grid = (B + BM - 1) / BM;

    pfn_encode_t enc = get_encoder();
    if (!enc) return;   // should never happen; avoids host crash -> container death

    CUtensorMap tmx, tmw;
    make_map_2d(&tmx, enc, x,  D_IN, (uint64_t)B, BK, BM);  // x: [B, 1280] row-major
    make_map_2d(&tmw, enc, W1, D_IN, 64,          BK, 64);  // W1: [64, 1280]

    const size_t smem_bytes = (size_t)NSTAGE * STAGE_BYTES + 1024;  // 99328 B

    cudaFuncSetAttribute(qh_fused_kernel,
                         cudaFuncAttributeMaxDynamicSharedMemorySize, (int)smem_bytes);
    qh_fused_kernel<<<grid, NTHREADS, smem_bytes>>>(tmx, tmw, b1, bn_g, bn_b, bn_m, bn_v,
                                                    W2, b2, qw, W3, b3, out, B);
}

// round 7
// speedup vs baseline: 1.0270x; 1.0270x over previous
#include <cuda_runtime.h>
#include <cuda.h>
#include <cstdint>

#define D_IN      1280
#define BM        128
#define BK        32
#define NSTAGE    4
#define NTHREADS  256
#define XTILE_FLOATS (BM * BK)                    // 4096 floats = 16 KB
#define WTILE_FLOATS (64 * BK)                    // 2048 floats = 8 KB
#define STAGE_FLOATS (XTILE_FLOATS + WTILE_FLOATS)// 6144 floats = 24 KB
#define STAGE_BYTES  (STAGE_FLOATS * 4)
#define HS_STRIDE 65

// ---------------- PTX helpers ----------------
__device__ __forceinline__ unsigned f2tf(float f) {
    unsigned r; asm("cvt.rna.tf32.f32 %0, %1;\n" : "=r"(r) : "f"(f)); return r;
}
__device__ __forceinline__ void mma8(float& c0, float& c1, float& c2, float& c3,
                                     unsigned a0, unsigned a1, unsigned a2, unsigned a3,
                                     unsigned b0, unsigned b1) {
    asm volatile("mma.sync.aligned.m16n8k8.row.col.f32.tf32.tf32.f32 "
                 "{%0,%1,%2,%3}, {%4,%5,%6,%7}, {%8,%9}, {%0,%1,%2,%3};\n"
                 : "+f"(c0), "+f"(c1), "+f"(c2), "+f"(c3)
                 : "r"(a0), "r"(a1), "r"(a2), "r"(a3), "r"(b0), "r"(b1));
}
__device__ __forceinline__ void mbar_wait_acq(unsigned addr, unsigned parity) {
    asm volatile(
        "{\n\t.reg .pred P1;\n\t"
        "WAIT_%=:\n\t"
        "mbarrier.try_wait.parity.acquire.cta.shared::cta.b64 P1, [%0], %1, 0x989680;\n\t"
        "@P1 bra.uni DONE_%=;\n\t"
        "bra.uni WAIT_%=;\n\t"
        "DONE_%=:\n\t}"
        :: "r"(addr), "r"(parity) : "memory");
}
__device__ __forceinline__ void mbar_wait_rlx(unsigned addr, unsigned parity) {
    asm volatile(
        "{\n\t.reg .pred P1;\n\t"
        "WAIT_%=:\n\t"
        "mbarrier.try_wait.parity.relaxed.cta.shared::cta.b64 P1, [%0], %1, 0x989680;\n\t"
        "@P1 bra.uni DONE_%=;\n\t"
        "bra.uni WAIT_%=;\n\t"
        "DONE_%=:\n\t}"
        :: "r"(addr), "r"(parity) : "memory");
}
__device__ __forceinline__ void mbar_arrive(unsigned addr) {
    asm volatile("mbarrier.arrive.shared.b64 _, [%0];" :: "r"(addr) : "memory");
}
__device__ __forceinline__ void tma2d(unsigned saddr, const CUtensorMap* tm,
                                      int cx, int cy, unsigned mbar) {
    asm volatile("cp.async.bulk.tensor.2d.shared::cta.global.tile.mbarrier::complete_tx::bytes "
                 "[%0], [%1, {%2, %3}], [%4];"
                 :: "r"(saddr), "l"(tm), "r"(cx), "r"(cy), "r"(mbar) : "memory");
}

// ---------------- fused kernel ----------------
// h = relu(x@W1^T+b1); h = h*scale+shift (BN eval); xq = tanh(h@W2^T+b2);
// 4-qubit sim with angles pi*tanh(xq); out = z@W3^T+b3.
__global__ __launch_bounds__(NTHREADS, 2)
void qh_fused_kernel(const __grid_constant__ CUtensorMap tmx,
                     const __grid_constant__ CUtensorMap tmw,
                     const float* __restrict__ b1,  const float* __restrict__ bn_g,
                     const float* __restrict__ bn_b,const float* __restrict__ bn_m,
                     const float* __restrict__ bn_v,const float* __restrict__ W2,
                     const float* __restrict__ b2,  const float* __restrict__ qw,
                     const float* __restrict__ W3,  const float* __restrict__ b3,
                     float* __restrict__ out, int B)
{
    extern __shared__ float smem_raw[];
    float* smem = (float*)(((uintptr_t)smem_raw + 1023) & ~(uintptr_t)1023); // SW128 tile base
    __shared__ __align__(8) unsigned long long mbar_full[NSTAGE];
    __shared__ __align__(8) unsigned long long mbar_empty[NSTAGE];
    __shared__ float bias_s[64], scale_s[64], shift_s[64];
    __shared__ float w2s[256], b2s[4], w3s[40], b3s[10];
    __shared__ float ryc[8], rys[8], rzc[8], rzs[8];

    const int tid = threadIdx.x;
    const int blockRow = blockIdx.x * BM;

    // ---- per-block parameter prep (tiny) ----
    if (tid < 64) {
        float rs = rsqrtf(bn_v[tid] + 1e-5f);
        float sc = bn_g[tid] * rs;
        scale_s[tid] = sc;
        shift_s[tid] = bn_b[tid] - bn_m[tid] * sc;
        bias_s[tid]  = b1[tid];
    }
    if (tid < 256) w2s[tid] = W2[tid];
    if (tid < 16) {
        int l = (tid >> 2) & 1, qi = tid & 3, isRz = tid >> 3;
        float half = 0.5f * qw[l * 8 + qi * 2 + isRz];
        float sv, cv; sincosf(half, &sv, &cv);
        if (isRz) { rzc[l*4+qi] = cv; rzs[l*4+qi] = sv; }
        else      { ryc[l*4+qi] = cv; rys[l*4+qi] = sv; }
    }
    if (tid < 40) w3s[tid] = W3[tid];
    if (tid < 10) b3s[tid] = b3[tid];
    if (tid < 4)  b2s[tid] = b2[tid];

    // ---- mbarrier init ----
    if (tid == 0) {
        #pragma unroll
        for (int s = 0; s < NSTAGE; s++) {
            unsigned fa = (unsigned)__cvta_generic_to_shared(&mbar_full[s]);
            unsigned ea = (unsigned)__cvta_generic_to_shared(&mbar_empty[s]);
            asm volatile("mbarrier.init.shared.b64 [%0], 1;" :: "r"(fa) : "memory");
            asm volatile("mbarrier.init.shared.b64 [%0], 8;" :: "r"(ea) : "memory");
        }
        asm volatile("fence.proxy.async.shared::cta;" ::: "memory");
    }
    __syncthreads();

    const int KT = D_IN / BK;   // 40
    auto issue_stage = [&](int st) {
        float* xs = smem + (st & (NSTAGE - 1)) * STAGE_FLOATS;
        unsigned xaddr = (unsigned)__cvta_generic_to_shared(xs);
        unsigned waddr = xaddr + XTILE_FLOATS * 4;
        unsigned ma = (unsigned)__cvta_generic_to_shared(&mbar_full[st & (NSTAGE - 1)]);
        asm volatile("mbarrier.arrive.expect_tx.shared.b64 _, [%0], %1;"
                     :: "r"(ma), "r"((unsigned)STAGE_BYTES) : "memory");
        tma2d(xaddr, &tmx, st * BK, blockRow, ma);
        tma2d(waddr, &tmw, st * BK, 0, ma);
    };
    if (tid == 0) {
        #pragma unroll
        for (int s = 0; s < NSTAGE - 1; s++) issue_stage(s);   // rounds 0: no empty-wait
    }

    const int lane = tid & 31, warp = tid >> 5;      // 8 warps
    const int warpRow = warp >> 1;                   // 0..3 -> 32-row band
    const int warpCol = warp & 1;                    // 0..1 -> 32-col band
    const int g = lane >> 2, t = lane & 3;

    float acc[2][4][4];
    #pragma unroll
    for (int mt = 0; mt < 2; mt++)
        #pragma unroll
        for (int nt = 0; nt < 4; nt++)
            #pragma unroll
            for (int k = 0; k < 4; k++) acc[mt][nt][k] = 0.f;

    for (int kt = 0; kt < KT; kt++) {
        const int buf = kt & (NSTAGE - 1);
        const unsigned u = (unsigned)kt >> 2;

        // producer: refill stage kt+NSTAGE-1 once all 8 warps released its buffer
        if (tid == 0) {
            const int st = kt + NSTAGE - 1;
            if (st < KT) {
                const int sb = st & (NSTAGE - 1);
                const unsigned su = (unsigned)st >> 2;
                if (su > 0)
                    mbar_wait_rlx((unsigned)__cvta_generic_to_shared(&mbar_empty[sb]),
                                  (su - 1) & 1);
                issue_stage(st);
            }
        }

        // consumer: wait for this stage's TMA data
        mbar_wait_acq((unsigned)__cvta_generic_to_shared(&mbar_full[buf]), u & 1);

        // SW128-swizzled tiles: float (r, c) at r*32 + (((c>>2) ^ (r&7))<<2) + (c&3)
        const float* xs = smem + buf * STAGE_FLOATS;
        const float* ws = xs + XTILE_FLOATS;
        const float* xsb = xs + (warpRow * 32 + g) * 32 + t;   // (r&7) == g for all our rows
        const float* wsb = ws + (warpCol * 32 + g) * 32 + t;

        #pragma unroll
        for (int k8 = 0; k8 < BK / 8; k8++) {
            const int c0 = ((2 * k8)     ^ g) << 2;
            const int c1 = ((2 * k8 + 1) ^ g) << 2;
            unsigned a[2][4], b[4][2];
            #pragma unroll
            for (int mt = 0; mt < 2; mt++) {
                const float* p = xsb + mt * 16 * 32;
                a[mt][0] = f2tf(p[c0]);
                a[mt][1] = f2tf(p[8 * 32 + c0]);
                a[mt][2] = f2tf(p[c1]);
                a[mt][3] = f2tf(p[8 * 32 + c1]);
            }
            #pragma unroll
            for (int nt = 0; nt < 4; nt++) {
                const float* p = wsb + nt * 8 * 32;
                b[nt][0] = f2tf(p[c0]);
                b[nt][1] = f2tf(p[c1]);
            }
            #pragma unroll
            for (int mt = 0; mt < 2; mt++)
                #pragma unroll
                for (int nt = 0; nt < 4; nt++)
                    mma8(acc[mt][nt][0], acc[mt][nt][1], acc[mt][nt][2], acc[mt][nt][3],
                         a[mt][0], a[mt][1], a[mt][2], a[mt][3], b[nt][0], b[nt][1]);
        }

        // release buffer: all lanes' reads done, then one arrive per warp
        __syncwarp();
        if (lane == 0)
            mbar_arrive((unsigned)__cvta_generic_to_shared(&mbar_empty[buf]));
    }
    __syncthreads();   // all warps done with all stage buffers

    // ---- epilogue: bias+relu+BN, stage h-tile to smem ----
    float* hs = smem;  // overlay (33 KB << 96 KB pipeline buffers)
    #pragma unroll
    for (int mt = 0; mt < 2; mt++) {
        const int r0 = warpRow * 32 + mt * 16 + g;
        #pragma unroll
        for (int nt = 0; nt < 4; nt++) {
            const int n0 = warpCol * 32 + nt * 8 + t * 2;
            float s0 = scale_s[n0],  s1 = scale_s[n0 + 1];
            float f0 = shift_s[n0],  f1 = shift_s[n0 + 1];
            float bi0 = bias_s[n0],  bi1 = bias_s[n0 + 1];
            hs[r0 * HS_STRIDE + n0]           = fmaxf(acc[mt][nt][0] + bi0, 0.f) * s0 + f0;
            hs[r0 * HS_STRIDE + n0 + 1]       = fmaxf(acc[mt][nt][1] + bi1, 0.f) * s1 + f1;
            hs[(r0 + 8) * HS_STRIDE + n0]     = fmaxf(acc[mt][nt][2] + bi0, 0.f) * s0 + f0;
            hs[(r0 + 8) * HS_STRIDE + n0 + 1] = fmaxf(acc[mt][nt][3] + bi1, 0.f) * s1 + f1;
        }
    }
    __syncthreads();

    // ---- one thread per row: W2 proj + 4-qubit statevector sim + W3 out ----
    const int gr = blockRow + tid;
    if (tid < BM && gr < B) {
        float aq0 = b2s[0], aq1 = b2s[1], aq2 = b2s[2], aq3 = b2s[3];
        const float* hr = hs + tid * HS_STRIDE;
        #pragma unroll
        for (int j = 0; j < 64; j++) {
            float v = hr[j];
            aq0 += v * w2s[j];        aq1 += v * w2s[64 + j];
            aq2 += v * w2s[128 + j];  aq3 += v * w2s[192 + j];
        }
        float aq[4] = {aq0, aq1, aq2, aq3};
        float ci[4], si[4];
        #pragma unroll
        for (int i = 0; i < 4; i++) {
            // half-angle = (pi/2) * tanh(tanh(pre))  (double tanh is faithful to reference)
            float hl = 1.57079632679489662f * tanhf(tanhf(aq[i]));
            sincosf(hl, &si[i], &ci[i]);
        }
        // initial RY layer on |0000>: real product state. bit of wire i = (s >> (3-i)) & 1
        float re[16], im[16];
        #pragma unroll
        for (int s = 0; s < 16; s++) {
            float p = ((s >> 3) & 1 ? si[0] : ci[0]);
            p *=      ((s >> 2) & 1 ? si[1] : ci[1]);
            p *=      ((s >> 1) & 1 ? si[2] : ci[2]);
            p *=      ((s     ) & 1 ? si[3] : ci[3]);
            re[s] = p; im[s] = 0.f;
        }
        #pragma unroll
        for (int l = 0; l < 2; l++) {
            #pragma unroll
            for (int qi = 0; qi < 4; qi++) {
                const int m = 1 << (3 - qi);
                float c = ryc[l * 4 + qi], sv = rys[l * 4 + qi];
                #pragma unroll
                for (int s0 = 0; s0 < 16; s0++) {
                    if (!(s0 & m)) {
                        const int s1 = s0 | m;
                        float r0 = re[s0], r1 = re[s1], i0 = im[s0], i1 = im[s1];
                        re[s0] = c * r0 - sv * r1;  im[s0] = c * i0 - sv * i1;
                        re[s1] = sv * r0 + c * r1;  im[s1] = sv * i0 + c * i1;
                    }
                }
                float ch = rzc[l * 4 + qi], sh = rzs[l * 4 + qi];
                #pragma unroll
                for (int s0 = 0; s0 < 16; s0++) {
                    float r = re[s0], iz = im[s0];
                    if (!(s0 & m)) { re[s0] = r * ch + iz * sh; im[s0] = iz * ch - r * sh; }
                    else           { re[s0] = r * ch - iz * sh; im[s0] = iz * ch + r * sh; }
                }
            }
            #pragma unroll
            for (int qi = 0; qi < 4; qi++) {        // CNOT(qi, (qi+1)%4), in order
                const int mc = 1 << (3 - qi);
                const int mt_ = 1 << (3 - ((qi + 1) & 3));
                #pragma unroll
                for (int s0 = 0; s0 < 16; s0++) {
                    if ((s0 & mc) && !(s0 & mt_)) {
                        const int s1 = s0 | mt_;
                        float tr = re[s0]; re[s0] = re[s1]; re[s1] = tr;
                        float ti = im[s0]; im[s0] = im[s1]; im[s1] = ti;
                    }
                }
            }
        }
        float z0 = 0.f, z1 = 0.f, z2 = 0.f, z3 = 0.f;
        #pragma unroll
        for (int s = 0; s < 16; s++) {
            float p = re[s] * re[s] + im[s] * im[s];
            z0 += (s & 8) ? -p : p;
            z1 += (s & 4) ? -p : p;
            z2 += (s & 2) ? -p : p;
            z3 += (s & 1) ? -p : p;
        }
        #pragma unroll
        for (int c = 0; c < 10; c++) {
            out[(size_t)gr * 10 + c] = b3s[c] + w3s[c * 4 + 0] * z0 + w3s[c * 4 + 1] * z1
                                              + w3s[c * 4 + 2] * z2 + w3s[c * 4 + 3] * z3;
        }
    }
}

// ---------------- host: tensor maps + launch ----------------
typedef CUresult (*pfn_encode_t)(CUtensorMap*, CUtensorMapDataType, cuuint32_t, void*,
                                 const cuuint64_t*, const cuuint64_t*, const cuuint32_t*,
                                 const cuuint32_t*, CUtensorMapInterleave, CUtensorMapSwizzle,
                                 CUtensorMapL2promotion, CUtensorMapFloatOOBfill);

static pfn_encode_t get_encoder() {
    void* fn = nullptr;
    cudaDriverEntryPointQueryResult qr = cudaDriverEntryPointSymbolNotFound;
    if (cudaGetDriverEntryPointByVersion("cuTensorMapEncodeTiled", &fn, 12000,
                                         cudaEnableDefault, &qr) == cudaSuccess &&
        qr == cudaDriverEntryPointSuccess && fn) return (pfn_encode_t)fn;
    fn = nullptr;
    if (cudaGetDriverEntryPoint("cuTensorMapEncodeTiled", &fn,
                                cudaEnableDefault, &qr) == cudaSuccess &&
        qr == cudaDriverEntryPointSuccess && fn) return (pfn_encode_t)fn;
    return nullptr;
}

static void make_map_2d(CUtensorMap* m, pfn_encode_t enc, void* ptr,
                        uint64_t d0, uint64_t d1, uint32_t b0, uint32_t b1) {
    cuuint64_t dims[2]    = {d0, d1};
    cuuint64_t strides[1] = {d0 * 4};
    cuuint32_t box[2]     = {b0, b1};
    cuuint32_t es[2]      = {1, 1};
    enc(m, CU_TENSOR_MAP_DATA_TYPE_FLOAT32, 2, ptr, dims, strides, box, es,
        CU_TENSOR_MAP_INTERLEAVE_NONE, CU_TENSOR_MAP_SWIZZLE_128B,
        CU_TENSOR_MAP_L2_PROMOTION_L2_128B, CU_TENSOR_MAP_FLOAT_OOB_FILL_NONE);
}

extern "C" void kernel_launch(void* const* d_in, const int* in_sizes, int n_in,
                              void* d_out, int out_size) {
    void* x    = d_in[0];
    void* W1   = d_in[1];
    const float* b1   = (const float*)d_in[2];
    const float* bn_g = (const float*)d_in[3];
    const float* bn_b = (const float*)d_in[4];
    const float* bn_m = (const float*)d_in[5];
    const float* bn_v = (const float*)d_in[6];
    const float* W2   = (const float*)d_in[7];
    const float* b2   = (const float*)d_in[8];
    const float* qw   = (const float*)d_in[9];
    const float* W3   = (const float*)d_in[10];
    const float* b3   = (const float*)d_in[11];
    float* out = (float*)d_out;

    const int B = in_sizes[0] / D_IN;
    const int grid = (B + BM - 1) / BM;

    pfn_encode_t enc = get_encoder();
    if (!enc) return;

    CUtensorMap tmx, tmw;
    make_map_2d(&tmx, enc, x,  D_IN, (uint64_t)B, BK, BM);  // x: [B, 1280] row-major
    make_map_2d(&tmw, enc, W1, D_IN, 64,          BK, 64);  // W1: [64, 1280]

    const size_t smem_bytes = (size_t)NSTAGE * STAGE_BYTES + 1024;  // 99328 B

    cudaFuncSetAttribute(qh_fused_kernel,
                         cudaFuncAttributeMaxDynamicSharedMemorySize, (int)smem_bytes);
    qh_fused_kernel<<<grid, NTHREADS, smem_bytes>>>(tmx, tmw, b1, bn_g, bn_b, bn_m, bn_v,
                                                    W2, b2, qw, W3, b3, out, B);
}

// round 10
// speedup vs baseline: 1.1510x; 1.1207x over previous
#include <cuda_runtime.h>
#include <cstdint>

#define D_IN      1280
#define H_DIM     64
#define BM        128
#define BK        16
#define NSTAGE    4
#define KT        (D_IN / BK)                 // 80
#define XS_STRIDE 20                          // banks (20g+t)%32 all-distinct for frag LDS
#define STAGE_FLOATS ((BM + H_DIM) * XS_STRIDE)   // 192*20 = 3840 floats = 15360 B
#define HS_STRIDE 65

// W1 pre-rounded to tf32-RNA (bits exact under the MMA's tf32 read)
__device__ float g_w1t[H_DIM * D_IN];

// ---------------- PTX helpers ----------------
__device__ __forceinline__ void cp16(void* dst, const void* src) {
    unsigned s = (unsigned)__cvta_generic_to_shared(dst);
    asm volatile("cp.async.cg.shared.global [%0], [%1], 16;\n" :: "r"(s), "l"(src));
}
__device__ __forceinline__ void cp_commit() { asm volatile("cp.async.commit_group;\n"); }
template<int N> __device__ __forceinline__ void cp_wait() {
    asm volatile("cp.async.wait_group %0;\n" :: "n"(N));
}
__device__ __forceinline__ unsigned f2tf(float f) {
    unsigned r; asm("cvt.rna.tf32.f32 %0, %1;\n" : "=r"(r) : "f"(f)); return r;
}
__device__ __forceinline__ void mma8(float& c0, float& c1, float& c2, float& c3,
                                     unsigned a0, unsigned a1, unsigned a2, unsigned a3,
                                     unsigned b0, unsigned b1) {
    asm volatile("mma.sync.aligned.m16n8k8.row.col.f32.tf32.tf32.f32 "
                 "{%0,%1,%2,%3}, {%4,%5,%6,%7}, {%8,%9}, {%0,%1,%2,%3};\n"
                 : "+f"(c0), "+f"(c1), "+f"(c2), "+f"(c3)
                 : "r"(a0), "r"(a1), "r"(a2), "r"(a3), "r"(b0), "r"(b1));
}

// ---------------- W1 -> tf32-RNA scratch ----------------
__global__ void prep_w1_kernel(const float* __restrict__ W1) {
    int i = blockIdx.x * blockDim.x + threadIdx.x;
    if (i < H_DIM * D_IN) g_w1t[i] = __uint_as_float(f2tf(W1[i]));
}

// ---------------- fused kernel ----------------
// h = relu(x@W1^T+b1); h = h*scale+shift (BN eval); xq = tanh(h@W2^T+b2);
// 4-qubit sim with angles pi*tanh(xq); out = z@W3^T+b3.
__global__ __launch_bounds__(128, 3)
void qh_fused_kernel(const float* __restrict__ x,
                     const float* __restrict__ b1,  const float* __restrict__ bn_g,
                     const float* __restrict__ bn_b,const float* __restrict__ bn_m,
                     const float* __restrict__ bn_v,const float* __restrict__ W2,
                     const float* __restrict__ b2,  const float* __restrict__ qw,
                     const float* __restrict__ W3,  const float* __restrict__ b3,
                     float* __restrict__ out, int B)
{
    extern __shared__ float smem[];     // NSTAGE stages; reused as h-tile in epilogue
    __shared__ float bias_s[64], scale_s[64], shift_s[64];
    __shared__ float w2s[256], b2s[4], w3s[40], b3s[10];
    __shared__ float ryc[8], rys[8], rzc[8], rzs[8];

    const int tid = threadIdx.x;
    const int blockRow = blockIdx.x * BM;

    // ---- per-block parameter prep (tiny) ----
    if (tid < 64) {
        float rs = rsqrtf(bn_v[tid] + 1e-5f);
        float sc = bn_g[tid] * rs;
        scale_s[tid] = sc;
        shift_s[tid] = bn_b[tid] - bn_m[tid] * sc;
        bias_s[tid]  = b1[tid];
    }
    for (int i = tid; i < 256; i += 128) w2s[i] = W2[i];
    if (tid < 16) {
        int l = (tid >> 2) & 1, qi = tid & 3, isRz = tid >> 3;
        float half = 0.5f * qw[l * 8 + qi * 2 + isRz];
        float sv, cv; sincosf(half, &sv, &cv);
        if (isRz) { rzc[l*4+qi] = cv; rzs[l*4+qi] = sv; }
        else      { ryc[l*4+qi] = cv; rys[l*4+qi] = sv; }
    }
    if (tid < 40) w3s[tid] = W3[tid];
    if (tid < 10) b3s[tid] = b3[tid];
    if (tid < 4)  b2s[tid] = b2[tid];

    // ---- async-pipelined tf32 GEMM: [BM x 64] += x-tile @ W1-tile^T ----
    auto prefetch = [&](int kt) {
        if (kt < KT) {
            float* xs = smem + (kt & (NSTAGE - 1)) * STAGE_FLOATS;
            float* ws = xs + BM * XS_STRIDE;
            const int k0 = kt * BK;
            #pragma unroll
            for (int i = 0; i < 4; i++) {           // x tile: 128 rows x 16 cols (4 chunks/row)
                int c = i * 128 + tid;
                int row = c >> 2, ch = c & 3;
                int gr = blockRow + row; if (gr >= B) gr = B - 1;
                cp16(&xs[row * XS_STRIDE + ch * 4], &x[(size_t)gr * D_IN + k0 + ch * 4]);
            }
            #pragma unroll
            for (int i = 0; i < 2; i++) {           // W1(tf32) tile: 64 rows x 16 cols
                int c = i * 128 + tid;
                int row = c >> 2, ch = c & 3;
                cp16(&ws[row * XS_STRIDE + ch * 4], &g_w1t[(size_t)row * D_IN + k0 + ch * 4]);
            }
        }
        cp_commit();
    };

    const int lane = tid & 31, warp = tid >> 5;   // 4 warps, each a 32-row band x full N=64
    const int g = lane >> 2, t = lane & 3;

    float acc[2][8][4];
    #pragma unroll
    for (int mt = 0; mt < 2; mt++)
        #pragma unroll
        for (int nt = 0; nt < 8; nt++)
            #pragma unroll
            for (int k = 0; k < 4; k++) acc[mt][nt][k] = 0.f;

    #pragma unroll
    for (int i = 0; i < NSTAGE - 1; i++) prefetch(i);

    for (int kt = 0; kt < KT; kt++) {
        cp_wait<NSTAGE - 2>();
        __syncthreads();
        prefetch(kt + NSTAGE - 1);

        const float* xs = smem + (kt & (NSTAGE - 1)) * STAGE_FLOATS;
        const float* ws = xs + BM * XS_STRIDE;
        const float* arow = xs + (warp * 32 + g) * XS_STRIDE + t;
        const float* brow = ws + g * XS_STRIDE + t;

        #pragma unroll
        for (int k8 = 0; k8 < BK / 8; k8++) {
            const int kb = k8 * 8;
            unsigned a[2][4], b[8][2];
            #pragma unroll
            for (int mt = 0; mt < 2; mt++) {
                const float* p = arow + mt * 16 * XS_STRIDE + kb;
                a[mt][0] = f2tf(p[0]);
                a[mt][1] = f2tf(p[8 * XS_STRIDE]);
                a[mt][2] = f2tf(p[4]);
                a[mt][3] = f2tf(p[8 * XS_STRIDE + 4]);
            }
            #pragma unroll
            for (int nt = 0; nt < 8; nt++) {        // W1 pre-rounded: raw bits == tf32-RNA
                const float* p = brow + nt * 8 * XS_STRIDE + kb;
                b[nt][0] = __float_as_uint(p[0]);
                b[nt][1] = __float_as_uint(p[4]);
            }
            #pragma unroll
            for (int mt = 0; mt < 2; mt++)
                #pragma unroll
                for (int nt = 0; nt < 8; nt++)
                    mma8(acc[mt][nt][0], acc[mt][nt][1], acc[mt][nt][2], acc[mt][nt][3],
                         a[mt][0], a[mt][1], a[mt][2], a[mt][3], b[nt][0], b[nt][1]);
        }
    }
    __syncthreads();   // all warps done reading stage buffers

    // ---- epilogue: bias+relu+BN, stage h-tile to smem ----
    float* hs = smem;  // [BM][HS_STRIDE] overlay (33 KB < 61 KB pipeline buffers)
    #pragma unroll
    for (int mt = 0; mt < 2; mt++) {
        const int r0 = warp * 32 + mt * 16 + g;
        #pragma unroll
        for (int nt = 0; nt < 8; nt++) {
            const int n0 = nt * 8 + t * 2;
            float s0 = scale_s[n0],  s1 = scale_s[n0 + 1];
            float f0 = shift_s[n0],  f1 = shift_s[n0 + 1];
            float bi0 = bias_s[n0],  bi1 = bias_s[n0 + 1];
            hs[r0 * HS_STRIDE + n0]           = fmaxf(acc[mt][nt][0] + bi0, 0.f) * s0 + f0;
            hs[r0 * HS_STRIDE + n0 + 1]       = fmaxf(acc[mt][nt][1] + bi1, 0.f) * s1 + f1;
            hs[(r0 + 8) * HS_STRIDE + n0]     = fmaxf(acc[mt][nt][2] + bi0, 0.f) * s0 + f0;
            hs[(r0 + 8) * HS_STRIDE + n0 + 1] = fmaxf(acc[mt][nt][3] + bi1, 0.f) * s1 + f1;
        }
    }
    __syncthreads();

    // ---- one thread per row: W2 proj + 4-qubit statevector sim + W3 out ----
    const int gr = blockRow + tid;
    if (gr < B) {
        float aq0 = b2s[0], aq1 = b2s[1], aq2 = b2s[2], aq3 = b2s[3];
        const float* hr = hs + tid * HS_STRIDE;
        #pragma unroll
        for (int j = 0; j < 64; j++) {
            float v = hr[j];
            aq0 += v * w2s[j];        aq1 += v * w2s[64 + j];
            aq2 += v * w2s[128 + j];  aq3 += v * w2s[192 + j];
        }
        float aq[4] = {aq0, aq1, aq2, aq3};
        float ci[4], si[4];
        #pragma unroll
        for (int i = 0; i < 4; i++) {
            // half-angle = (pi/2) * tanh(tanh(pre))  (double tanh is faithful to reference)
            float hl = 1.57079632679489662f * tanhf(tanhf(aq[i]));
            sincosf(hl, &si[i], &ci[i]);
        }
        // initial RY layer on |0000>: real product state. bit of wire i = (s >> (3-i)) & 1
        float re[16], im[16];
        #pragma unroll
        for (int s = 0; s < 16; s++) {
            float p = ((s >> 3) & 1 ? si[0] : ci[0]);
            p *=      ((s >> 2) & 1 ? si[1] : ci[1]);
            p *=      ((s >> 1) & 1 ? si[2] : ci[2]);
            p *=      ((s     ) & 1 ? si[3] : ci[3]);
            re[s] = p; im[s] = 0.f;
        }
        #pragma unroll
        for (int l = 0; l < 2; l++) {
            #pragma unroll
            for (int qi = 0; qi < 4; qi++) {
                const int m = 1 << (3 - qi);
                float c = ryc[l * 4 + qi], sv = rys[l * 4 + qi];
                #pragma unroll
                for (int s0 = 0; s0 < 16; s0++) {
                    if (!(s0 & m)) {
                        const int s1 = s0 | m;
                        float r0 = re[s0], r1 = re[s1], i0 = im[s0], i1 = im[s1];
                        re[s0] = c * r0 - sv * r1;  im[s0] = c * i0 - sv * i1;
                        re[s1] = sv * r0 + c * r1;  im[s1] = sv * i0 + c * i1;
                    }
                }
                float ch = rzc[l * 4 + qi], sh = rzs[l * 4 + qi];
                #pragma unroll
                for (int s0 = 0; s0 < 16; s0++) {
                    float r = re[s0], iz = im[s0];
                    if (!(s0 & m)) { re[s0] = r * ch + iz * sh; im[s0] = iz * ch - r * sh; }
                    else           { re[s0] = r * ch - iz * sh; im[s0] = iz * ch + r * sh; }
                }
            }
            #pragma unroll
            for (int qi = 0; qi < 4; qi++) {        // CNOT(qi, (qi+1)%4), in order
                const int mc = 1 << (3 - qi);
                const int mt_ = 1 << (3 - ((qi + 1) & 3));
                #pragma unroll
                for (int s0 = 0; s0 < 16; s0++) {
                    if ((s0 & mc) && !(s0 & mt_)) {
                        const int s1 = s0 | mt_;
                        float tr = re[s0]; re[s0] = re[s1]; re[s1] = tr;
                        float ti = im[s0]; im[s0] = im[s1]; im[s1] = ti;
                    }
                }
            }
        }
        float z0 = 0.f, z1 = 0.f, z2 = 0.f, z3 = 0.f;
        #pragma unroll
        for (int s = 0; s < 16; s++) {
            float p = re[s] * re[s] + im[s] * im[s];
            z0 += (s & 8) ? -p : p;
            z1 += (s & 4) ? -p : p;
            z2 += (s & 2) ? -p : p;
            z3 += (s & 1) ? -p : p;
        }
        #pragma unroll
        for (int c = 0; c < 10; c++) {
            out[(size_t)gr * 10 + c] = b3s[c] + w3s[c * 4 + 0] * z0 + w3s[c * 4 + 1] * z1
                                              + w3s[c * 4 + 2] * z2 + w3s[c * 4 + 3] * z3;
        }
    }
}

// ---------------- launch ----------------
extern "C" void kernel_launch(void* const* d_in, const int* in_sizes, int n_in,
                              void* d_out, int out_size) {
    const float* x    = (const float*)d_in[0];
    const float* W1   = (const float*)d_in[1];
    const float* b1   = (const float*)d_in[2];
    const float* bn_g = (const float*)d_in[3];
    const float* bn_b = (const float*)d_in[4];
    const float* bn_m = (const float*)d_in[5];
    const float* bn_v = (const float*)d_in[6];
    const float* W2   = (const float*)d_in[7];
    const float* b2   = (const float*)d_in[8];
    const float* qw   = (const float*)d_in[9];
    const float* W3   = (const float*)d_in[10];
    const float* b3   = (const float*)d_in[11];
    float* out = (float*)d_out;

    const int B = in_sizes[0] / D_IN;
    const int grid = (B + BM - 1) / BM;
    const size_t smem_bytes = (size_t)NSTAGE * STAGE_FLOATS * sizeof(float); // 61440 B

    prep_w1_kernel<<<(H_DIM * D_IN + 255) / 256, 256>>>(W1);

    cudaFuncSetAttribute(qh_fused_kernel,
                         cudaFuncAttributeMaxDynamicSharedMemorySize, (int)smem_bytes);
    qh_fused_kernel<<<grid, 128, smem_bytes>>>(x, b1, bn_g, bn_b, bn_m, bn_v,
                                               W2, b2, qw, W3, b3, out, B);
}